// round 16
// baseline (speedup 1.0000x reference)
#include <cuda_runtime.h>
#include <math.h>

#define Hdim   1024
#define H2     512
#define Cdim   256
#define Msize  100000
#define Nsamp  1024
#define Tlen   1024
#define G3     3072
#define RCTAS  64           // CTAs per layer (total grid = 128)
#define RUPC   16           // hidden units per CTA (one per warp, 512 threads)

// ---------------- scratch (static __device__, no allocs) ----------------
__device__ __align__(16) float d_samples[Nsamp * Hdim];
__device__ __align__(16) float d_e1[Nsamp * H2];
__device__ __align__(16) float d_encoded[Nsamp * H2];
__device__ __align__(16) float d_zbuf[Nsamp * Cdim];
__device__ __align__(16) float d_d1[Nsamp * H2];
__device__ __align__(16) float d_recon[Nsamp * Hdim];
__device__ __align__(16) float d_gx[Tlen * G3];        // layer-0 input gates (GEMM)
__device__ __align__(16) float d_gx1[Tlen * G3];       // layer-1 input gates (fused)
__device__ __align__(16) float d_wout[Tlen * Hdim];
__device__ float d_toterr[Nsamp];
__device__ __align__(16) float g_h0[2][Hdim];
__device__ __align__(16) float g_h1[2][Hdim];
__device__ unsigned cnt0[Tlen + 1];
__device__ unsigned cnt1[Tlen];

__device__ __forceinline__ float gelu_exact(float x) {
    return 0.5f * x * (1.0f + erff(x * 0.7071067811865476f));
}
__device__ __forceinline__ float sigmoidf_(float x) {
    return 1.0f / (1.0f + expf(-x));
}
__device__ __forceinline__ void red_add_release(unsigned* p, unsigned v) {
    asm volatile("red.add.release.gpu.global.u32 [%0], %1;" :: "l"(p), "r"(v) : "memory");
}
__device__ __forceinline__ unsigned ld_acquire(const unsigned* p) {
    unsigned v;
    asm volatile("ld.acquire.gpu.global.u32 %0, [%1];" : "=r"(v) : "l"(p) : "memory");
    return v;
}

// ---------------- init / small utility kernels ----------------
__global__ void init_kernel() {
    int i = blockIdx.x * blockDim.x + threadIdx.x;    // 8 x 256 = 2048
    if (i < 2 * Hdim) {
        ((float*)g_h0)[i] = 0.0f;
        ((float*)g_h1)[i] = 0.0f;
    }
    if (i < Tlen + 1) cnt0[i] = 0u;
    if (i < Tlen) cnt1[i] = 0u;
}

__global__ void gather_kernel(const float* __restrict__ mem, const int* __restrict__ idx) {
    int n = blockIdx.x;                               // 1024 blocks, 256 threads
    const float4* src = (const float4*)(mem + (size_t)idx[n] * Hdim);
    float4* dst = (float4*)(d_samples + (size_t)n * Hdim);
    dst[threadIdx.x] = src[threadIdx.x];
}

// ---------------- SGEMM 128x128x8, double-buffered: C = A@W^T + bias -------
#define TBM 128
#define TBN 128
#define TBK 8
__global__ void __launch_bounds__(256)
sgemm_bias_kernel(const float* __restrict__ A, const float* __restrict__ W,
                  const float* __restrict__ bias, float* __restrict__ C,
                  int M, int N, int K) {
    __shared__ float As[2][TBK][TBM];
    __shared__ float Bs[2][TBK][TBN];
    const int tid = threadIdx.x;                      // 256
    const int tx = tid & 15, ty = tid >> 4;
    const int row0 = blockIdx.y * TBM, col0 = blockIdx.x * TBN;
    const int lr = tid >> 1;                          // 0..127
    const int lk = (tid & 1) * 4;                     // 0 or 4
    const float* Ap = A + (size_t)(row0 + lr) * K + lk;
    const float* Wp = W + (size_t)(col0 + lr) * K + lk;

    {
        float4 a = *(const float4*)Ap;
        float4 b = *(const float4*)Wp;
        As[0][lk + 0][lr] = a.x; As[0][lk + 1][lr] = a.y;
        As[0][lk + 2][lr] = a.z; As[0][lk + 3][lr] = a.w;
        Bs[0][lk + 0][lr] = b.x; Bs[0][lk + 1][lr] = b.y;
        Bs[0][lk + 2][lr] = b.z; Bs[0][lk + 3][lr] = b.w;
    }
    __syncthreads();

    float acc[8][8];
#pragma unroll
    for (int i = 0; i < 8; i++)
#pragma unroll
        for (int j = 0; j < 8; j++) acc[i][j] = 0.0f;

    const int nIter = K / TBK;
    int cur = 0;
    for (int it = 0; it < nIter; ++it) {
        float4 an, bn;
        const bool more = (it + 1 < nIter);
        if (more) {
            an = *(const float4*)(Ap + (it + 1) * TBK);
            bn = *(const float4*)(Wp + (it + 1) * TBK);
        }
#pragma unroll
        for (int k = 0; k < TBK; k++) {
            float af[8], bf[8];
            *(float4*)&af[0] = *(const float4*)&As[cur][k][ty * 8];
            *(float4*)&af[4] = *(const float4*)&As[cur][k][ty * 8 + 4];
            *(float4*)&bf[0] = *(const float4*)&Bs[cur][k][tx * 8];
            *(float4*)&bf[4] = *(const float4*)&Bs[cur][k][tx * 8 + 4];
#pragma unroll
            for (int i = 0; i < 8; i++)
#pragma unroll
                for (int j = 0; j < 8; j++) acc[i][j] += af[i] * bf[j];
        }
        if (more) {
            int nxt = cur ^ 1;
            As[nxt][lk + 0][lr] = an.x; As[nxt][lk + 1][lr] = an.y;
            As[nxt][lk + 2][lr] = an.z; As[nxt][lk + 3][lr] = an.w;
            Bs[nxt][lk + 0][lr] = bn.x; Bs[nxt][lk + 1][lr] = bn.y;
            Bs[nxt][lk + 2][lr] = bn.z; Bs[nxt][lk + 3][lr] = bn.w;
            __syncthreads();
            cur = nxt;
        }
    }

    float bc[8];
#pragma unroll
    for (int j = 0; j < 8; j++) bc[j] = bias[col0 + tx * 8 + j];
#pragma unroll
    for (int i = 0; i < 8; i++) {
        float* Cr = C + (size_t)(row0 + ty * 8 + i) * N + col0 + tx * 8;
        float4 v0 = make_float4(acc[i][0] + bc[0], acc[i][1] + bc[1],
                                acc[i][2] + bc[2], acc[i][3] + bc[3]);
        float4 v1 = make_float4(acc[i][4] + bc[4], acc[i][5] + bc[5],
                                acc[i][6] + bc[6], acc[i][7] + bc[7]);
        *(float4*)Cr = v0;
        *(float4*)(Cr + 4) = v1;
    }
}

// ---------------- LayerNorm(512) + exact GELU, in place ----------------
__global__ void ln_gelu_kernel(float* __restrict__ x, const float* __restrict__ g,
                               const float* __restrict__ b) {
    int row = blockIdx.x, tid = threadIdx.x;          // 128 threads, 4 elems each
    float4* xr = (float4*)(x + (size_t)row * H2);
    float4 v = xr[tid];
    float s = v.x + v.y + v.z + v.w;
    __shared__ float red[8];
#pragma unroll
    for (int o = 16; o > 0; o >>= 1) s += __shfl_xor_sync(0xffffffffu, s, o);
    if ((tid & 31) == 0) red[tid >> 5] = s;
    __syncthreads();
    float mean = (red[0] + red[1] + red[2] + red[3]) * (1.0f / 512.0f);
    float dx = v.x - mean, dy = v.y - mean, dz = v.z - mean, dw = v.w - mean;
    float q = dx * dx + dy * dy + dz * dz + dw * dw;
#pragma unroll
    for (int o = 16; o > 0; o >>= 1) q += __shfl_xor_sync(0xffffffffu, q, o);
    if ((tid & 31) == 0) red[4 + (tid >> 5)] = q;
    __syncthreads();
    float var = (red[4] + red[5] + red[6] + red[7]) * (1.0f / 512.0f);
    float rstd = rsqrtf(var + 1e-5f);
    float4 gg = ((const float4*)g)[tid];
    float4 bb = ((const float4*)b)[tid];
    v.x = gelu_exact(dx * rstd * gg.x + bb.x);
    v.y = gelu_exact(dy * rstd * gg.y + bb.y);
    v.z = gelu_exact(dz * rstd * gg.z + bb.z);
    v.w = gelu_exact(dw * rstd * gg.w + bb.w);
    xr[tid] = v;
}

// ---------------- reparameterize ----------------
__global__ void reparam_kernel(const float* __restrict__ eps) {
    int i = blockIdx.x * blockDim.x + threadIdx.x;    // N*C = 262144
    if (i < Nsamp * Cdim) {
        int n = i >> 8, c = i & 255;
        float mu = d_encoded[(size_t)n * H2 + c];
        float lv = d_encoded[(size_t)n * H2 + 256 + c];
        d_zbuf[i] = mu + expf(0.5f * lv) * eps[i];
    }
}

// ---------------- pipelined 2-layer GRU recurrence ----------------
// Grid = 128 CTAs x 512 threads, all co-resident.
// CTAs 0..63 (role 0): layer-0 recurrence with gx1 slack work SPLIT across two
//   windows (double-buffered h_s):
//     window A (during h broadcast): warps 8..15 compute gx1[t-2] rows 0..23
//       from h[t-1] (preserved buffer);
//     window B (during barrier):     warps 1..7  compute gx1[t-1] rows 24..47
//       from hcur. Warp 0 never does slack work.
//   gx1[tau] complete by step tau+2 -> covered by layer-1's cnt0[s+3] gate.
// CTAs 64..127 (role 1): lean layer-1 recurrence (R15 exact).
__global__ void __launch_bounds__(512, 1)
gru_pipe_kernel(const float* __restrict__ whh0, const float* __restrict__ bhh0,
                const float* __restrict__ whh1, const float* __restrict__ bhh1,
                const float* __restrict__ wih1, const float* __restrict__ bih1) {
    extern __shared__ float smem_dyn[];
    float* h_s = smem_dyn;                    // 2*Hdim (double buffer)
    float* w1s = smem_dyn + 2 * Hdim;         // 48*Hdim (role 0 only)
    const int tid = threadIdx.x;
    const int warp = tid >> 5, lane = tid & 31;
    const bool role1 = (blockIdx.x >= RCTAS);
    const int cid = role1 ? (blockIdx.x - RCTAS) : blockIdx.x;
    const int u = cid * RUPC + warp;
    const float* whh = role1 ? whh1 : whh0;
    const float* bhh = role1 ? bhh1 : bhh0;

    // whh rows (r,z,n) for unit u -> registers. lane l owns cols k = 4l + 128j.
    float4 wr[8], wz[8], wn[8];
#pragma unroll
    for (int j = 0; j < 8; j++) {
        int k = 4 * lane + 128 * j;
        wr[j] = __ldg((const float4*)(whh + (size_t)(0 * Hdim + u) * Hdim + k));
        wz[j] = __ldg((const float4*)(whh + (size_t)(1 * Hdim + u) * Hdim + k));
        wn[j] = __ldg((const float4*)(whh + (size_t)(2 * Hdim + u) * Hdim + k));
    }
    const float br = bhh[u], bz = bhh[Hdim + u], bn = bhh[2 * Hdim + u];

    if (!role1) {
        // ---- layer 0 ----
        // wih1 rows for units 16*cid..16*cid+15 (48 rows) -> smem
        for (int i = tid; i < 48 * 256; i += 512) {
            int lr = i >> 8, pos = (i & 255) << 2;
            int grow = (lr >> 4) * Hdim + RUPC * cid + (lr & 15);
            *(float4*)(w1s + lr * Hdim + pos) =
                __ldg((const float4*)(wih1 + (size_t)grow * Hdim + pos));
        }
        // per-warp gx1 row lists
        // window A: warps 8..15 -> rows 3*(w-8)+{0,1,2}        (rows 0..23)
        // window B: warps 1..7  -> rows 24+3*(w-1)+{0,1,2}     (rows 24..44)
        //                          + warps 1..3 take rows 45..47
        int rws[4] = {-1, -1, -1, -1};
        if (warp >= 8) {
            rws[0] = 3 * (warp - 8); rws[1] = rws[0] + 1; rws[2] = rws[0] + 2;
        } else if (warp >= 1) {
            rws[0] = 24 + 3 * (warp - 1); rws[1] = rws[0] + 1; rws[2] = rws[0] + 2;
            if (warp <= 3) rws[3] = 44 + warp;
        }
        float bws[4] = {0.f, 0.f, 0.f, 0.f};
#pragma unroll
        for (int i = 0; i < 4; i++) {
            if (rws[i] >= 0) {
                int r = rws[i];
                bws[i] = bih1[(r >> 4) * Hdim + RUPC * cid + (r & 15)];
            }
        }
        __syncthreads();

        // compute gx1 rows for output step tout using hidden vector hbuf
        auto gx1_calc = [&](const float* hbuf, int tout) {
            const float* p0 = w1s + rws[0] * Hdim;
            const float* p1 = w1s + rws[1] * Hdim;
            const float* p2 = w1s + rws[2] * Hdim;
            const float* p3 = (rws[3] >= 0) ? (w1s + rws[3] * Hdim) : p0;
            float a0 = 0.f, a1 = 0.f, a2 = 0.f, a3 = 0.f;
#pragma unroll
            for (int j = 0; j < 8; ++j) {
                int p = lane + 32 * j;
                float4 h4 = ((const float4*)hbuf)[p];
                float4 w0 = ((const float4*)p0)[p];
                float4 w1 = ((const float4*)p1)[p];
                float4 w2 = ((const float4*)p2)[p];
                float4 w3 = ((const float4*)p3)[p];
                a0 += w0.x * h4.x + w0.y * h4.y + w0.z * h4.z + w0.w * h4.w;
                a1 += w1.x * h4.x + w1.y * h4.y + w1.z * h4.z + w1.w * h4.w;
                a2 += w2.x * h4.x + w2.y * h4.y + w2.z * h4.z + w2.w * h4.w;
                a3 += w3.x * h4.x + w3.y * h4.y + w3.z * h4.z + w3.w * h4.w;
            }
#pragma unroll
            for (int o = 16; o > 0; o >>= 1) {
                a0 += __shfl_xor_sync(0xffffffffu, a0, o);
                a1 += __shfl_xor_sync(0xffffffffu, a1, o);
                a2 += __shfl_xor_sync(0xffffffffu, a2, o);
                a3 += __shfl_xor_sync(0xffffffffu, a3, o);
            }
            if (lane == 0) {
                size_t ob = (size_t)tout * G3;
                int r0 = rws[0], r1 = rws[1], r2 = rws[2];
                d_gx1[ob + (r0 >> 4) * Hdim + RUPC * cid + (r0 & 15)] = a0 + bws[0];
                d_gx1[ob + (r1 >> 4) * Hdim + RUPC * cid + (r1 & 15)] = a1 + bws[1];
                d_gx1[ob + (r2 >> 4) * Hdim + RUPC * cid + (r2 & 15)] = a2 + bws[2];
                if (rws[3] >= 0) {
                    int r3 = rws[3];
                    d_gx1[ob + (r3 >> 4) * Hdim + RUPC * cid + (r3 & 15)] = a3 + bws[3];
                }
            }
        };

        float gxr = __ldg(d_gx + u), gxz = __ldg(d_gx + Hdim + u),
              gxn = __ldg(d_gx + 2 * Hdim + u);

        for (int t = 0; t < Tlen; ++t) {
            float* hcur = h_s + (t & 1) * Hdim;
            const float* hprev = h_s + ((t + 1) & 1) * Hdim;   // h[t-1]
            if (tid < 256) {
                float4 v = __ldcg(((const float4*)g_h0[t & 1]) + tid);
                *(float4*)(hcur + tid * 4) = v;
            } else if (t > 1 && warp >= 8) {
                gx1_calc(hprev, t - 2);       // window A: gx1[t-2] rows 0..23
            }
            __syncthreads();
            float sr = 0.f, sz = 0.f, sn = 0.f;
#pragma unroll
            for (int j = 0; j < 8; ++j) {
                float4 h4 = ((const float4*)hcur)[lane + 32 * j];
                sr += wr[j].x * h4.x + wr[j].y * h4.y + wr[j].z * h4.z + wr[j].w * h4.w;
                sz += wz[j].x * h4.x + wz[j].y * h4.y + wz[j].z * h4.z + wz[j].w * h4.w;
                sn += wn[j].x * h4.x + wn[j].y * h4.y + wn[j].z * h4.z + wn[j].w * h4.w;
            }
#pragma unroll
            for (int o = 16; o > 0; o >>= 1) {
                sr += __shfl_xor_sync(0xffffffffu, sr, o);
                sz += __shfl_xor_sync(0xffffffffu, sz, o);
                sn += __shfl_xor_sync(0xffffffffu, sn, o);
            }
            if (lane == 0) {
                float r = sigmoidf_(gxr + sr + br);
                float z = sigmoidf_(gxz + sz + bz);
                float nn = tanhf(gxn + r * (sn + bn));
                float hp = hcur[u];
                float hnew = (1.0f - z) * nn + z * hp;
                g_h0[(t + 1) & 1][u] = hnew;
            }
            if (t + 1 < Tlen) {
                const float* gp = d_gx + (size_t)(t + 1) * G3;
                gxr = __ldg(gp + u); gxz = __ldg(gp + Hdim + u); gxn = __ldg(gp + 2 * Hdim + u);
            }
            __syncthreads();
            if (t > 0 && warp >= 1 && warp <= 7)
                gx1_calc(hcur, t - 1);        // window B: gx1[t-1] rows 24..47
            if (tid == 0) {
                red_add_release(&cnt0[t], 1u);
                while (ld_acquire(&cnt0[t]) < (unsigned)RCTAS) { }
            }
            __syncthreads();
        }
        // epilogue: finish gx1[Tlen-2] rows 0..23 (from h[Tlen-1], preserved in
        // buffer (Tlen-1)&1) and all of gx1[Tlen-1] (from h[Tlen]).
        {
            float* hlast = h_s + (Tlen & 1) * Hdim;
            const float* hm1 = h_s + ((Tlen - 1) & 1) * Hdim;  // h[Tlen-1]
            if (tid < 256) {
                float4 v = __ldcg(((const float4*)g_h0[Tlen & 1]) + tid);
                *(float4*)(hlast + tid * 4) = v;
            } else if (warp >= 8) {
                gx1_calc(hm1, Tlen - 2);      // rows 0..23 of gx1[Tlen-2]
            }
            __syncthreads();
            if (warp >= 8) gx1_calc(hlast, Tlen - 1);          // rows 0..23
            if (warp >= 1 && warp <= 7) gx1_calc(hlast, Tlen - 1); // rows 24..47
            __syncthreads();
            if (tid == 0) red_add_release(&cnt0[Tlen], 1u);
        }
    } else {
        // ---- layer 1 (R15 exact) ----
        if (tid == 0) {
            while (ld_acquire(&cnt0[2]) < (unsigned)RCTAS) { }
        }
        __syncthreads();
        float gxr = __ldcg(d_gx1 + u), gxz = __ldcg(d_gx1 + Hdim + u),
              gxn = __ldcg(d_gx1 + 2 * Hdim + u);

        for (int s = 0; s < Tlen; ++s) {
            float* hcur = h_s;                // single buffer is fine for layer 1
            if (tid < 256) {
                float4 v = __ldcg(((const float4*)g_h1[s & 1]) + tid);
                *(float4*)(hcur + tid * 4) = v;
            }
            __syncthreads();
            float sr = 0.f, sz = 0.f, sn = 0.f;
#pragma unroll
            for (int j = 0; j < 8; ++j) {
                float4 h4 = ((const float4*)hcur)[lane + 32 * j];
                sr += wr[j].x * h4.x + wr[j].y * h4.y + wr[j].z * h4.z + wr[j].w * h4.w;
                sz += wz[j].x * h4.x + wz[j].y * h4.y + wz[j].z * h4.z + wz[j].w * h4.w;
                sn += wn[j].x * h4.x + wn[j].y * h4.y + wn[j].z * h4.z + wn[j].w * h4.w;
            }
#pragma unroll
            for (int o = 16; o > 0; o >>= 1) {
                sr += __shfl_xor_sync(0xffffffffu, sr, o);
                sz += __shfl_xor_sync(0xffffffffu, sz, o);
                sn += __shfl_xor_sync(0xffffffffu, sn, o);
            }
            if (lane == 0) {
                float r = sigmoidf_(gxr + sr + br);
                float z = sigmoidf_(gxz + sz + bz);
                float nn = tanhf(gxn + r * (sn + bn));
                float hp = hcur[u];
                float hnew = (1.0f - z) * nn + z * hp;
                g_h1[(s + 1) & 1][u] = hnew;
                d_wout[(size_t)s * Hdim + u] = hnew;
            }
            __syncthreads();
            if (tid == 0) {
                red_add_release(&cnt1[s], 1u);
                if (s + 1 < Tlen) {
                    int ws = s + 3 < Tlen ? s + 3 : Tlen;
                    bool a = false, b = false;
                    for (;;) {
                        if (!a) a = (ld_acquire(&cnt1[s]) >= (unsigned)RCTAS);
                        if (!b) b = (ld_acquire(&cnt0[ws]) >= (unsigned)RCTAS);
                        if (a && b) break;
                    }
                } else {
                    while (ld_acquire(&cnt1[s]) < (unsigned)RCTAS) { }
                }
            }
            __syncthreads();
            if (s + 1 < Tlen) {
                const float* gp = d_gx1 + (size_t)(s + 1) * G3;
                gxr = __ldcg(gp + u); gxz = __ldcg(gp + Hdim + u);
                gxn = __ldcg(gp + 2 * Hdim + u);
            }
        }
    }
}

// ---------------- losses ----------------
__global__ void loss_kernel() {
    int n = blockIdx.x, tid = threadIdx.x;            // 256 threads
    int warp = tid >> 5, lane = tid & 31;
    float sr = 0.f, sw = 0.f;
    for (int i = tid; i < Hdim; i += 256) {
        float s = d_samples[(size_t)n * Hdim + i];
        float a = d_recon[(size_t)n * Hdim + i] - s;
        float b = d_wout[(size_t)n * Hdim + i] - s;
        sr += a * a;
        sw += b * b;
    }
    float mu = d_encoded[(size_t)n * H2 + tid];
    float lv = d_encoded[(size_t)n * H2 + 256 + tid];
    float sk = 1.0f + lv - mu * mu - expf(lv);
    __shared__ float rbuf[24];
#pragma unroll
    for (int o = 16; o > 0; o >>= 1) {
        sr += __shfl_xor_sync(0xffffffffu, sr, o);
        sw += __shfl_xor_sync(0xffffffffu, sw, o);
        sk += __shfl_xor_sync(0xffffffffu, sk, o);
    }
    if (lane == 0) { rbuf[warp] = sr; rbuf[8 + warp] = sw; rbuf[16 + warp] = sk; }
    __syncthreads();
    if (tid == 0) {
        float tr = 0.f, tw = 0.f, tk = 0.f;
        for (int w = 0; w < 8; ++w) { tr += rbuf[w]; tw += rbuf[8 + w]; tk += rbuf[16 + w]; }
        d_toterr[n] = tr * (1.0f / 1024.0f) + 0.1f * tw * (1.0f / 1024.0f)
                    + 0.001f * (-0.5f * tk);
    }
}

__global__ void mean_kernel(float* __restrict__ out) {
    int tid = threadIdx.x;                            // 256
    int warp = tid >> 5, lane = tid & 31;
    float s = 0.f;
    for (int i = tid; i < Nsamp; i += 256) s += d_toterr[i];
    __shared__ float rbuf[8];
#pragma unroll
    for (int o = 16; o > 0; o >>= 1) s += __shfl_xor_sync(0xffffffffu, s, o);
    if (lane == 0) rbuf[warp] = s;
    __syncthreads();
    if (tid == 0) {
        float t = 0.f;
        for (int w = 0; w < 8; ++w) t += rbuf[w];
        out[0] = t * (1.0f / (float)Nsamp);
    }
}

__global__ void copy_imp_kernel(const float* __restrict__ imp, float* __restrict__ out) {
    int i = blockIdx.x * blockDim.x + threadIdx.x;
    if (i < Msize) out[1 + i] = imp[i];
}

// duplicate indices: last occurrence in idx order wins (serial scatter semantics)
__global__ void scatter_kernel(const int* __restrict__ idx, const float* __restrict__ imp,
                               float* __restrict__ out) {
    int i = blockIdx.x * blockDim.x + threadIdx.x;
    if (i < Nsamp) {
        int d = idx[i];
        bool last = true;
        for (int j = i + 1; j < Nsamp; ++j)
            if (idx[j] == d) { last = false; break; }
        if (last) out[1 + d] = 0.9f * imp[d] + 0.1f * d_toterr[i];
    }
}

// ---------------- launch ----------------
extern "C" void kernel_launch(void* const* d_in, const int* in_sizes, int n_in,
                              void* d_out, int out_size) {
    (void)n_in; (void)out_size;
    const float *episodic, *memimp, *eps;
    const int* idx;
    const float *enc_w1, *enc_b1, *enc_g, *enc_beta, *enc_w2, *enc_b2;
    const float *dec_w1, *dec_b1, *dec_g, *dec_beta, *dec_w2, *dec_b2;
    const float *wih0, *whh0, *bih0, *bhh0, *wih1, *whh1, *bih1, *bhh1;

    if (in_sizes[3] == Nsamp) {
        episodic = (const float*)d_in[0];  memimp = (const float*)d_in[1];
        eps = (const float*)d_in[2];       idx = (const int*)d_in[3];
        enc_w1 = (const float*)d_in[4];    enc_b1 = (const float*)d_in[5];
        enc_g = (const float*)d_in[6];     enc_beta = (const float*)d_in[7];
        enc_w2 = (const float*)d_in[8];    enc_b2 = (const float*)d_in[9];
        dec_w1 = (const float*)d_in[10];   dec_b1 = (const float*)d_in[11];
        dec_g = (const float*)d_in[12];    dec_beta = (const float*)d_in[13];
        dec_w2 = (const float*)d_in[14];   dec_b2 = (const float*)d_in[15];
        wih0 = (const float*)d_in[16];     whh0 = (const float*)d_in[17];
        bih0 = (const float*)d_in[18];     bhh0 = (const float*)d_in[19];
        wih1 = (const float*)d_in[20];     whh1 = (const float*)d_in[21];
        bih1 = (const float*)d_in[22];     bhh1 = (const float*)d_in[23];
    } else {
        episodic = (const float*)d_in[0];  memimp = (const float*)d_in[1];
        eps = (const float*)d_in[2];
        enc_w1 = (const float*)d_in[3];    enc_b1 = (const float*)d_in[4];
        enc_g = (const float*)d_in[5];     enc_beta = (const float*)d_in[6];
        enc_w2 = (const float*)d_in[7];    enc_b2 = (const float*)d_in[8];
        dec_w1 = (const float*)d_in[9];    dec_b1 = (const float*)d_in[10];
        dec_g = (const float*)d_in[11];    dec_beta = (const float*)d_in[12];
        dec_w2 = (const float*)d_in[13];   dec_b2 = (const float*)d_in[14];
        wih0 = (const float*)d_in[15];     whh0 = (const float*)d_in[16];
        bih0 = (const float*)d_in[17];     bhh0 = (const float*)d_in[18];
        wih1 = (const float*)d_in[19];     whh1 = (const float*)d_in[20];
        bih1 = (const float*)d_in[21];     bhh1 = (const float*)d_in[22];
        idx = (const int*)d_in[23];
    }
    float* out = (float*)d_out;

    float *p_samples, *p_e1, *p_encoded, *p_z, *p_d1, *p_recon, *p_gx;
    cudaGetSymbolAddress((void**)&p_samples, d_samples);
    cudaGetSymbolAddress((void**)&p_e1, d_e1);
    cudaGetSymbolAddress((void**)&p_encoded, d_encoded);
    cudaGetSymbolAddress((void**)&p_z, d_zbuf);
    cudaGetSymbolAddress((void**)&p_d1, d_d1);
    cudaGetSymbolAddress((void**)&p_recon, d_recon);
    cudaGetSymbolAddress((void**)&p_gx, d_gx);

    const size_t pipe_smem = (size_t)(2 * Hdim + 48 * Hdim) * sizeof(float);  // 204800
    cudaFuncSetAttribute(gru_pipe_kernel, cudaFuncAttributeMaxDynamicSharedMemorySize,
                         (int)pipe_smem);

    init_kernel<<<8, 256>>>();
    gather_kernel<<<Nsamp, 256>>>(episodic, idx);

    // encoder
    sgemm_bias_kernel<<<dim3(H2 / TBN, Nsamp / TBM), 256>>>(p_samples, enc_w1, enc_b1, p_e1,
                                                            Nsamp, H2, Hdim);
    ln_gelu_kernel<<<Nsamp, 128>>>(p_e1, enc_g, enc_beta);
    sgemm_bias_kernel<<<dim3(H2 / TBN, Nsamp / TBM), 256>>>(p_e1, enc_w2, enc_b2, p_encoded,
                                                            Nsamp, H2, H2);
    reparam_kernel<<<(Nsamp * Cdim) / 256, 256>>>(eps);

    // decoder
    sgemm_bias_kernel<<<dim3(H2 / TBN, Nsamp / TBM), 256>>>(p_z, dec_w1, dec_b1, p_d1,
                                                            Nsamp, H2, Cdim);
    ln_gelu_kernel<<<Nsamp, 128>>>(p_d1, dec_g, dec_beta);
    sgemm_bias_kernel<<<dim3(Hdim / TBN, Nsamp / TBM), 256>>>(p_d1, dec_w2, dec_b2, p_recon,
                                                              Nsamp, Hdim, H2);

    // layer-0 input gates, then BOTH GRU layers pipelined in one kernel
    sgemm_bias_kernel<<<dim3(G3 / TBN, Nsamp / TBM), 256>>>(p_recon, wih0, bih0, p_gx,
                                                            Nsamp, G3, Hdim);
    gru_pipe_kernel<<<2 * RCTAS, 512, pipe_smem>>>(whh0, bhh0, whh1, bhh1, wih1, bih1);

    // losses + outputs
    loss_kernel<<<Nsamp, 256>>>();
    mean_kernel<<<1, 256>>>(out);
    copy_imp_kernel<<<(Msize + 255) / 256, 256>>>(memimp, out);
    scatter_kernel<<<4, 256>>>(idx, memimp, out);
}

// round 17
// speedup vs baseline: 1.3834x; 1.3834x over previous
#include <cuda_runtime.h>
#include <math.h>

#define Hdim   1024
#define H2     512
#define Cdim   256
#define Msize  100000
#define Nsamp  1024
#define Tlen   1024
#define G3     3072
#define RCTAS  64           // CTAs per layer (total grid = 128)
#define RUPC   16           // hidden units per CTA (one per warp, 512 threads)

// ---------------- scratch (static __device__, no allocs) ----------------
__device__ __align__(16) float d_samples[Nsamp * Hdim];
__device__ __align__(16) float d_e1[Nsamp * H2];
__device__ __align__(16) float d_encoded[Nsamp * H2];
__device__ __align__(16) float d_zbuf[Nsamp * Cdim];
__device__ __align__(16) float d_d1[Nsamp * H2];
__device__ __align__(16) float d_recon[Nsamp * Hdim];
__device__ __align__(16) float d_gx[Tlen * G3];        // layer-0 input gates (GEMM)
__device__ __align__(16) float d_gx1[Tlen * G3];       // layer-1 input gates (fused)
__device__ __align__(16) float d_wout[Tlen * Hdim];
__device__ float d_toterr[Nsamp];
__device__ __align__(16) float g_h0[2][Hdim];
__device__ __align__(16) float g_h1[2][Hdim];
__device__ unsigned cnt0[Tlen + 1];
__device__ unsigned cnt1[Tlen];

__device__ __forceinline__ float gelu_exact(float x) {
    return 0.5f * x * (1.0f + erff(x * 0.7071067811865476f));
}
__device__ __forceinline__ float sigmoidf_(float x) {
    return 1.0f / (1.0f + expf(-x));
}
__device__ __forceinline__ void red_add_release(unsigned* p, unsigned v) {
    asm volatile("red.add.release.gpu.global.u32 [%0], %1;" :: "l"(p), "r"(v) : "memory");
}
__device__ __forceinline__ unsigned ld_acquire(const unsigned* p) {
    unsigned v;
    asm volatile("ld.acquire.gpu.global.u32 %0, [%1];" : "=r"(v) : "l"(p) : "memory");
    return v;
}

// ---------------- init / small utility kernels ----------------
__global__ void init_kernel() {
    int i = blockIdx.x * blockDim.x + threadIdx.x;    // 8 x 256 = 2048
    if (i < 2 * Hdim) {
        ((float*)g_h0)[i] = 0.0f;
        ((float*)g_h1)[i] = 0.0f;
    }
    if (i < Tlen + 1) cnt0[i] = 0u;
    if (i < Tlen) cnt1[i] = 0u;
}

__global__ void gather_kernel(const float* __restrict__ mem, const int* __restrict__ idx) {
    int n = blockIdx.x;                               // 1024 blocks, 256 threads
    const float4* src = (const float4*)(mem + (size_t)idx[n] * Hdim);
    float4* dst = (float4*)(d_samples + (size_t)n * Hdim);
    dst[threadIdx.x] = src[threadIdx.x];
}

// ---------------- SGEMM 128x128x8 (for the big gx0 GEMM) -------------------
#define TBM 128
#define TBN 128
#define TBK 8
__global__ void __launch_bounds__(256)
sgemm_bias_kernel(const float* __restrict__ A, const float* __restrict__ W,
                  const float* __restrict__ bias, float* __restrict__ C,
                  int M, int N, int K) {
    __shared__ float As[2][TBK][TBM];
    __shared__ float Bs[2][TBK][TBN];
    const int tid = threadIdx.x;                      // 256
    const int tx = tid & 15, ty = tid >> 4;
    const int row0 = blockIdx.y * TBM, col0 = blockIdx.x * TBN;
    const int lr = tid >> 1;                          // 0..127
    const int lk = (tid & 1) * 4;                     // 0 or 4
    const float* Ap = A + (size_t)(row0 + lr) * K + lk;
    const float* Wp = W + (size_t)(col0 + lr) * K + lk;

    {
        float4 a = *(const float4*)Ap;
        float4 b = *(const float4*)Wp;
        As[0][lk + 0][lr] = a.x; As[0][lk + 1][lr] = a.y;
        As[0][lk + 2][lr] = a.z; As[0][lk + 3][lr] = a.w;
        Bs[0][lk + 0][lr] = b.x; Bs[0][lk + 1][lr] = b.y;
        Bs[0][lk + 2][lr] = b.z; Bs[0][lk + 3][lr] = b.w;
    }
    __syncthreads();

    float acc[8][8];
#pragma unroll
    for (int i = 0; i < 8; i++)
#pragma unroll
        for (int j = 0; j < 8; j++) acc[i][j] = 0.0f;

    const int nIter = K / TBK;
    int cur = 0;
    for (int it = 0; it < nIter; ++it) {
        float4 an, bn;
        const bool more = (it + 1 < nIter);
        if (more) {
            an = *(const float4*)(Ap + (it + 1) * TBK);
            bn = *(const float4*)(Wp + (it + 1) * TBK);
        }
#pragma unroll
        for (int k = 0; k < TBK; k++) {
            float af[8], bf[8];
            *(float4*)&af[0] = *(const float4*)&As[cur][k][ty * 8];
            *(float4*)&af[4] = *(const float4*)&As[cur][k][ty * 8 + 4];
            *(float4*)&bf[0] = *(const float4*)&Bs[cur][k][tx * 8];
            *(float4*)&bf[4] = *(const float4*)&Bs[cur][k][tx * 8 + 4];
#pragma unroll
            for (int i = 0; i < 8; i++)
#pragma unroll
                for (int j = 0; j < 8; j++) acc[i][j] += af[i] * bf[j];
        }
        if (more) {
            int nxt = cur ^ 1;
            As[nxt][lk + 0][lr] = an.x; As[nxt][lk + 1][lr] = an.y;
            As[nxt][lk + 2][lr] = an.z; As[nxt][lk + 3][lr] = an.w;
            Bs[nxt][lk + 0][lr] = bn.x; Bs[nxt][lk + 1][lr] = bn.y;
            Bs[nxt][lk + 2][lr] = bn.z; Bs[nxt][lk + 3][lr] = bn.w;
            __syncthreads();
            cur = nxt;
        }
    }

    float bc[8];
#pragma unroll
    for (int j = 0; j < 8; j++) bc[j] = bias[col0 + tx * 8 + j];
#pragma unroll
    for (int i = 0; i < 8; i++) {
        float* Cr = C + (size_t)(row0 + ty * 8 + i) * N + col0 + tx * 8;
        float4 v0 = make_float4(acc[i][0] + bc[0], acc[i][1] + bc[1],
                                acc[i][2] + bc[2], acc[i][3] + bc[3]);
        float4 v1 = make_float4(acc[i][4] + bc[4], acc[i][5] + bc[5],
                                acc[i][6] + bc[6], acc[i][7] + bc[7]);
        *(float4*)Cr = v0;
        *(float4*)(Cr + 4) = v1;
    }
}

// ---------------- SGEMM 64x64x16 (for the small GEMMs; more CTAs) ----------
#define BM 64
#define BN 64
#define BK 16
__global__ void __launch_bounds__(256)
sgemm64_bias_kernel(const float* __restrict__ A, const float* __restrict__ W,
                    const float* __restrict__ bias, float* __restrict__ C,
                    int M, int N, int K) {
    __shared__ float As[BK][BM + 4];
    __shared__ float Bs[BK][BN + 4];
    const int tid = threadIdx.x;                      // 256
    const int tx = tid & 15, ty = tid >> 4;
    const int row0 = blockIdx.y * BM, col0 = blockIdx.x * BN;
    const int lm = tid >> 2, lk = (tid & 3) * 4;
    const float* Ap = A + (size_t)(row0 + lm) * K + lk;
    const float* Wp = W + (size_t)(col0 + lm) * K + lk;
    float acc[4][4];
#pragma unroll
    for (int i = 0; i < 4; i++)
#pragma unroll
        for (int j = 0; j < 4; j++) acc[i][j] = 0.0f;

    for (int k0 = 0; k0 < K; k0 += BK) {
        float4 a = *(const float4*)(Ap + k0);
        float4 w = *(const float4*)(Wp + k0);
        __syncthreads();
        As[lk + 0][lm] = a.x; As[lk + 1][lm] = a.y; As[lk + 2][lm] = a.z; As[lk + 3][lm] = a.w;
        Bs[lk + 0][lm] = w.x; Bs[lk + 1][lm] = w.y; Bs[lk + 2][lm] = w.z; Bs[lk + 3][lm] = w.w;
        __syncthreads();
#pragma unroll
        for (int k = 0; k < BK; k++) {
            float4 av = *(const float4*)&As[k][ty * 4];
            float4 bv = *(const float4*)&Bs[k][tx * 4];
            acc[0][0] += av.x * bv.x; acc[0][1] += av.x * bv.y; acc[0][2] += av.x * bv.z; acc[0][3] += av.x * bv.w;
            acc[1][0] += av.y * bv.x; acc[1][1] += av.y * bv.y; acc[1][2] += av.y * bv.z; acc[1][3] += av.y * bv.w;
            acc[2][0] += av.z * bv.x; acc[2][1] += av.z * bv.y; acc[2][2] += av.z * bv.z; acc[2][3] += av.z * bv.w;
            acc[3][0] += av.w * bv.x; acc[3][1] += av.w * bv.y; acc[3][2] += av.w * bv.z; acc[3][3] += av.w * bv.w;
        }
    }
    float b0 = bias[col0 + tx * 4 + 0];
    float b1 = bias[col0 + tx * 4 + 1];
    float b2 = bias[col0 + tx * 4 + 2];
    float b3 = bias[col0 + tx * 4 + 3];
#pragma unroll
    for (int i = 0; i < 4; i++) {
        float* Cr = C + (size_t)(row0 + ty * 4 + i) * N + col0 + tx * 4;
        Cr[0] = acc[i][0] + b0;
        Cr[1] = acc[i][1] + b1;
        Cr[2] = acc[i][2] + b2;
        Cr[3] = acc[i][3] + b3;
    }
}

// ---------------- LayerNorm(512) + exact GELU, in place ----------------
__global__ void ln_gelu_kernel(float* __restrict__ x, const float* __restrict__ g,
                               const float* __restrict__ b) {
    int row = blockIdx.x, tid = threadIdx.x;          // 128 threads, 4 elems each
    float4* xr = (float4*)(x + (size_t)row * H2);
    float4 v = xr[tid];
    float s = v.x + v.y + v.z + v.w;
    __shared__ float red[8];
#pragma unroll
    for (int o = 16; o > 0; o >>= 1) s += __shfl_xor_sync(0xffffffffu, s, o);
    if ((tid & 31) == 0) red[tid >> 5] = s;
    __syncthreads();
    float mean = (red[0] + red[1] + red[2] + red[3]) * (1.0f / 512.0f);
    float dx = v.x - mean, dy = v.y - mean, dz = v.z - mean, dw = v.w - mean;
    float q = dx * dx + dy * dy + dz * dz + dw * dw;
#pragma unroll
    for (int o = 16; o > 0; o >>= 1) q += __shfl_xor_sync(0xffffffffu, q, o);
    if ((tid & 31) == 0) red[4 + (tid >> 5)] = q;
    __syncthreads();
    float var = (red[4] + red[5] + red[6] + red[7]) * (1.0f / 512.0f);
    float rstd = rsqrtf(var + 1e-5f);
    float4 gg = ((const float4*)g)[tid];
    float4 bb = ((const float4*)b)[tid];
    v.x = gelu_exact(dx * rstd * gg.x + bb.x);
    v.y = gelu_exact(dy * rstd * gg.y + bb.y);
    v.z = gelu_exact(dz * rstd * gg.z + bb.z);
    v.w = gelu_exact(dw * rstd * gg.w + bb.w);
    xr[tid] = v;
}

// ---------------- reparameterize ----------------
__global__ void reparam_kernel(const float* __restrict__ eps) {
    int i = blockIdx.x * blockDim.x + threadIdx.x;    // N*C = 262144
    if (i < Nsamp * Cdim) {
        int n = i >> 8, c = i & 255;
        float mu = d_encoded[(size_t)n * H2 + c];
        float lv = d_encoded[(size_t)n * H2 + 256 + c];
        d_zbuf[i] = mu + expf(0.5f * lv) * eps[i];
    }
}

// ---------------- pipelined 2-layer GRU recurrence (R15 exact) -------------
__global__ void __launch_bounds__(512, 1)
gru_pipe_kernel(const float* __restrict__ whh0, const float* __restrict__ bhh0,
                const float* __restrict__ whh1, const float* __restrict__ bhh1,
                const float* __restrict__ wih1, const float* __restrict__ bih1) {
    extern __shared__ float smem_dyn[];
    float* h_s = smem_dyn;                    // Hdim
    float* w1s = smem_dyn + Hdim;             // 48*Hdim (role 0 only)
    const int tid = threadIdx.x;
    const int warp = tid >> 5, lane = tid & 31;
    const bool role1 = (blockIdx.x >= RCTAS);
    const int cid = role1 ? (blockIdx.x - RCTAS) : blockIdx.x;
    const int u = cid * RUPC + warp;
    const float* whh = role1 ? whh1 : whh0;
    const float* bhh = role1 ? bhh1 : bhh0;

    float4 wr[8], wz[8], wn[8];
#pragma unroll
    for (int j = 0; j < 8; j++) {
        int k = 4 * lane + 128 * j;
        wr[j] = __ldg((const float4*)(whh + (size_t)(0 * Hdim + u) * Hdim + k));
        wz[j] = __ldg((const float4*)(whh + (size_t)(1 * Hdim + u) * Hdim + k));
        wn[j] = __ldg((const float4*)(whh + (size_t)(2 * Hdim + u) * Hdim + k));
    }
    const float br = bhh[u], bz = bhh[Hdim + u], bn = bhh[2 * Hdim + u];

    if (!role1) {
        // ---- layer 0 ----
        for (int i = tid; i < 48 * 256; i += 512) {
            int lr = i >> 8, pos = (i & 255) << 2;
            int grow = (lr >> 4) * Hdim + RUPC * cid + (lr & 15);
            *(float4*)(w1s + lr * Hdim + pos) =
                __ldg((const float4*)(wih1 + (size_t)grow * Hdim + pos));
        }
        const int base = warp - 1;
        float b1a = 0.f, b1b = 0.f, b1c = 0.f, b1d = 0.f;
        if (warp >= 1) {
            b1a = bih1[(base >> 4) * Hdim + RUPC * cid + (base & 15)];
            b1b = bih1[((base + 15) >> 4) * Hdim + RUPC * cid + ((base + 15) & 15)];
            b1c = bih1[((base + 30) >> 4) * Hdim + RUPC * cid + ((base + 30) & 15)];
            if (base + 45 < 48)
                b1d = bih1[((base + 45) >> 4) * Hdim + RUPC * cid + ((base + 45) & 15)];
        }
        __syncthreads();

        auto gx1_rows = [&](int tout) {
            const float* r0 = w1s + base * Hdim;
            const float* r1 = w1s + (base + 15) * Hdim;
            const float* r2 = w1s + (base + 30) * Hdim;
            const float* r3 = (base + 45 < 48) ? (w1s + (base + 45) * Hdim) : r0;
            float p0 = 0.f, p1 = 0.f, p2 = 0.f, p3 = 0.f;
#pragma unroll
            for (int j = 0; j < 8; ++j) {
                int p = lane + 32 * j;
                float4 h4 = ((const float4*)h_s)[p];
                float4 a = ((const float4*)r0)[p];
                float4 b = ((const float4*)r1)[p];
                float4 c = ((const float4*)r2)[p];
                float4 d = ((const float4*)r3)[p];
                p0 += a.x * h4.x + a.y * h4.y + a.z * h4.z + a.w * h4.w;
                p1 += b.x * h4.x + b.y * h4.y + b.z * h4.z + b.w * h4.w;
                p2 += c.x * h4.x + c.y * h4.y + c.z * h4.z + c.w * h4.w;
                p3 += d.x * h4.x + d.y * h4.y + d.z * h4.z + d.w * h4.w;
            }
#pragma unroll
            for (int o = 16; o > 0; o >>= 1) {
                p0 += __shfl_xor_sync(0xffffffffu, p0, o);
                p1 += __shfl_xor_sync(0xffffffffu, p1, o);
                p2 += __shfl_xor_sync(0xffffffffu, p2, o);
                p3 += __shfl_xor_sync(0xffffffffu, p3, o);
            }
            if (lane == 0) {
                size_t ob = (size_t)tout * G3;
                d_gx1[ob + (base >> 4) * Hdim + RUPC * cid + (base & 15)] = p0 + b1a;
                d_gx1[ob + ((base + 15) >> 4) * Hdim + RUPC * cid + ((base + 15) & 15)] = p1 + b1b;
                d_gx1[ob + ((base + 30) >> 4) * Hdim + RUPC * cid + ((base + 30) & 15)] = p2 + b1c;
                if (base + 45 < 48)
                    d_gx1[ob + ((base + 45) >> 4) * Hdim + RUPC * cid + ((base + 45) & 15)] = p3 + b1d;
            }
        };

        float gxr = __ldg(d_gx + u), gxz = __ldg(d_gx + Hdim + u),
              gxn = __ldg(d_gx + 2 * Hdim + u);

        for (int t = 0; t < Tlen; ++t) {
            if (tid < 256) {
                float4 v = __ldcg(((const float4*)g_h0[t & 1]) + tid);
                *(float4*)(h_s + tid * 4) = v;
            }
            __syncthreads();
            float sr = 0.f, sz = 0.f, sn = 0.f;
#pragma unroll
            for (int j = 0; j < 8; ++j) {
                float4 h4 = ((const float4*)h_s)[lane + 32 * j];
                sr += wr[j].x * h4.x + wr[j].y * h4.y + wr[j].z * h4.z + wr[j].w * h4.w;
                sz += wz[j].x * h4.x + wz[j].y * h4.y + wz[j].z * h4.z + wz[j].w * h4.w;
                sn += wn[j].x * h4.x + wn[j].y * h4.y + wn[j].z * h4.z + wn[j].w * h4.w;
            }
#pragma unroll
            for (int o = 16; o > 0; o >>= 1) {
                sr += __shfl_xor_sync(0xffffffffu, sr, o);
                sz += __shfl_xor_sync(0xffffffffu, sz, o);
                sn += __shfl_xor_sync(0xffffffffu, sn, o);
            }
            if (lane == 0) {
                float r = sigmoidf_(gxr + sr + br);
                float z = sigmoidf_(gxz + sz + bz);
                float nn = tanhf(gxn + r * (sn + bn));
                float hp = h_s[u];
                float hnew = (1.0f - z) * nn + z * hp;
                g_h0[(t + 1) & 1][u] = hnew;
            }
            if (t + 1 < Tlen) {
                const float* gp = d_gx + (size_t)(t + 1) * G3;
                gxr = __ldg(gp + u); gxz = __ldg(gp + Hdim + u); gxn = __ldg(gp + 2 * Hdim + u);
            }
            __syncthreads();
            if (t > 0 && warp != 0) gx1_rows(t - 1);   // slack work (h_s = y1[t-1])
            if (tid == 0) {
                red_add_release(&cnt0[t], 1u);
                while (ld_acquire(&cnt0[t]) < (unsigned)RCTAS) { }
            }
            __syncthreads();
        }
        // epilogue: gx1[Tlen-1] from h_Tlen
        if (tid < 256) {
            float4 v = __ldcg(((const float4*)g_h0[Tlen & 1]) + tid);
            *(float4*)(h_s + tid * 4) = v;
        }
        __syncthreads();
        if (warp != 0) gx1_rows(Tlen - 1);
        __syncthreads();
        if (tid == 0) red_add_release(&cnt0[Tlen], 1u);
    } else {
        // ---- layer 1 ----
        if (tid == 0) {
            while (ld_acquire(&cnt0[2]) < (unsigned)RCTAS) { }
        }
        __syncthreads();
        float gxr = __ldcg(d_gx1 + u), gxz = __ldcg(d_gx1 + Hdim + u),
              gxn = __ldcg(d_gx1 + 2 * Hdim + u);

        for (int s = 0; s < Tlen; ++s) {
            if (tid < 256) {
                float4 v = __ldcg(((const float4*)g_h1[s & 1]) + tid);
                *(float4*)(h_s + tid * 4) = v;
            }
            __syncthreads();
            float sr = 0.f, sz = 0.f, sn = 0.f;
#pragma unroll
            for (int j = 0; j < 8; ++j) {
                float4 h4 = ((const float4*)h_s)[lane + 32 * j];
                sr += wr[j].x * h4.x + wr[j].y * h4.y + wr[j].z * h4.z + wr[j].w * h4.w;
                sz += wz[j].x * h4.x + wz[j].y * h4.y + wz[j].z * h4.z + wz[j].w * h4.w;
                sn += wn[j].x * h4.x + wn[j].y * h4.y + wn[j].z * h4.z + wn[j].w * h4.w;
            }
#pragma unroll
            for (int o = 16; o > 0; o >>= 1) {
                sr += __shfl_xor_sync(0xffffffffu, sr, o);
                sz += __shfl_xor_sync(0xffffffffu, sz, o);
                sn += __shfl_xor_sync(0xffffffffu, sn, o);
            }
            if (lane == 0) {
                float r = sigmoidf_(gxr + sr + br);
                float z = sigmoidf_(gxz + sz + bz);
                float nn = tanhf(gxn + r * (sn + bn));
                float hp = h_s[u];
                float hnew = (1.0f - z) * nn + z * hp;
                g_h1[(s + 1) & 1][u] = hnew;
                d_wout[(size_t)s * Hdim + u] = hnew;
            }
            __syncthreads();
            if (tid == 0) {
                red_add_release(&cnt1[s], 1u);
                if (s + 1 < Tlen) {
                    int ws = s + 3 < Tlen ? s + 3 : Tlen;
                    bool a = false, b = false;
                    for (;;) {
                        if (!a) a = (ld_acquire(&cnt1[s]) >= (unsigned)RCTAS);
                        if (!b) b = (ld_acquire(&cnt0[ws]) >= (unsigned)RCTAS);
                        if (a && b) break;
                    }
                } else {
                    while (ld_acquire(&cnt1[s]) < (unsigned)RCTAS) { }
                }
            }
            __syncthreads();
            if (s + 1 < Tlen) {
                const float* gp = d_gx1 + (size_t)(s + 1) * G3;
                gxr = __ldcg(gp + u); gxz = __ldcg(gp + Hdim + u);
                gxn = __ldcg(gp + 2 * Hdim + u);
            }
        }
    }
}

// ---------------- losses ----------------
__global__ void loss_kernel() {
    int n = blockIdx.x, tid = threadIdx.x;            // 256 threads
    int warp = tid >> 5, lane = tid & 31;
    float sr = 0.f, sw = 0.f;
    for (int i = tid; i < Hdim; i += 256) {
        float s = d_samples[(size_t)n * Hdim + i];
        float a = d_recon[(size_t)n * Hdim + i] - s;
        float b = d_wout[(size_t)n * Hdim + i] - s;
        sr += a * a;
        sw += b * b;
    }
    float mu = d_encoded[(size_t)n * H2 + tid];
    float lv = d_encoded[(size_t)n * H2 + 256 + tid];
    float sk = 1.0f + lv - mu * mu - expf(lv);
    __shared__ float rbuf[24];
#pragma unroll
    for (int o = 16; o > 0; o >>= 1) {
        sr += __shfl_xor_sync(0xffffffffu, sr, o);
        sw += __shfl_xor_sync(0xffffffffu, sw, o);
        sk += __shfl_xor_sync(0xffffffffu, sk, o);
    }
    if (lane == 0) { rbuf[warp] = sr; rbuf[8 + warp] = sw; rbuf[16 + warp] = sk; }
    __syncthreads();
    if (tid == 0) {
        float tr = 0.f, tw = 0.f, tk = 0.f;
        for (int w = 0; w < 8; ++w) { tr += rbuf[w]; tw += rbuf[8 + w]; tk += rbuf[16 + w]; }
        d_toterr[n] = tr * (1.0f / 1024.0f) + 0.1f * tw * (1.0f / 1024.0f)
                    + 0.001f * (-0.5f * tk);
    }
}

__global__ void mean_kernel(float* __restrict__ out) {
    int tid = threadIdx.x;                            // 256
    int warp = tid >> 5, lane = tid & 31;
    float s = 0.f;
    for (int i = tid; i < Nsamp; i += 256) s += d_toterr[i];
    __shared__ float rbuf[8];
#pragma unroll
    for (int o = 16; o > 0; o >>= 1) s += __shfl_xor_sync(0xffffffffu, s, o);
    if (lane == 0) rbuf[warp] = s;
    __syncthreads();
    if (tid == 0) {
        float t = 0.f;
        for (int w = 0; w < 8; ++w) t += rbuf[w];
        out[0] = t * (1.0f / (float)Nsamp);
    }
}

__global__ void copy_imp_kernel(const float* __restrict__ imp, float* __restrict__ out) {
    int i = blockIdx.x * blockDim.x + threadIdx.x;
    if (i < Msize) out[1 + i] = imp[i];
}

// duplicate indices: last occurrence in idx order wins (serial scatter semantics)
__global__ void scatter_kernel(const int* __restrict__ idx, const float* __restrict__ imp,
                               float* __restrict__ out) {
    int i = blockIdx.x * blockDim.x + threadIdx.x;
    if (i < Nsamp) {
        int d = idx[i];
        bool last = true;
        for (int j = i + 1; j < Nsamp; ++j)
            if (idx[j] == d) { last = false; break; }
        if (last) out[1 + d] = 0.9f * imp[d] + 0.1f * d_toterr[i];
    }
}

// ---------------- launch ----------------
extern "C" void kernel_launch(void* const* d_in, const int* in_sizes, int n_in,
                              void* d_out, int out_size) {
    (void)n_in; (void)out_size;
    const float *episodic, *memimp, *eps;
    const int* idx;
    const float *enc_w1, *enc_b1, *enc_g, *enc_beta, *enc_w2, *enc_b2;
    const float *dec_w1, *dec_b1, *dec_g, *dec_beta, *dec_w2, *dec_b2;
    const float *wih0, *whh0, *bih0, *bhh0, *wih1, *whh1, *bih1, *bhh1;

    if (in_sizes[3] == Nsamp) {
        episodic = (const float*)d_in[0];  memimp = (const float*)d_in[1];
        eps = (const float*)d_in[2];       idx = (const int*)d_in[3];
        enc_w1 = (const float*)d_in[4];    enc_b1 = (const float*)d_in[5];
        enc_g = (const float*)d_in[6];     enc_beta = (const float*)d_in[7];
        enc_w2 = (const float*)d_in[8];    enc_b2 = (const float*)d_in[9];
        dec_w1 = (const float*)d_in[10];   dec_b1 = (const float*)d_in[11];
        dec_g = (const float*)d_in[12];    dec_beta = (const float*)d_in[13];
        dec_w2 = (const float*)d_in[14];   dec_b2 = (const float*)d_in[15];
        wih0 = (const float*)d_in[16];     whh0 = (const float*)d_in[17];
        bih0 = (const float*)d_in[18];     bhh0 = (const float*)d_in[19];
        wih1 = (const float*)d_in[20];     whh1 = (const float*)d_in[21];
        bih1 = (const float*)d_in[22];     bhh1 = (const float*)d_in[23];
    } else {
        episodic = (const float*)d_in[0];  memimp = (const float*)d_in[1];
        eps = (const float*)d_in[2];
        enc_w1 = (const float*)d_in[3];    enc_b1 = (const float*)d_in[4];
        enc_g = (const float*)d_in[5];     enc_beta = (const float*)d_in[6];
        enc_w2 = (const float*)d_in[7];    enc_b2 = (const float*)d_in[8];
        dec_w1 = (const float*)d_in[9];    dec_b1 = (const float*)d_in[10];
        dec_g = (const float*)d_in[11];    dec_beta = (const float*)d_in[12];
        dec_w2 = (const float*)d_in[13];   dec_b2 = (const float*)d_in[14];
        wih0 = (const float*)d_in[15];     whh0 = (const float*)d_in[16];
        bih0 = (const float*)d_in[17];     bhh0 = (const float*)d_in[18];
        wih1 = (const float*)d_in[19];     whh1 = (const float*)d_in[20];
        bih1 = (const float*)d_in[21];     bhh1 = (const float*)d_in[22];
        idx = (const int*)d_in[23];
    }
    float* out = (float*)d_out;

    float *p_samples, *p_e1, *p_encoded, *p_z, *p_d1, *p_recon, *p_gx;
    cudaGetSymbolAddress((void**)&p_samples, d_samples);
    cudaGetSymbolAddress((void**)&p_e1, d_e1);
    cudaGetSymbolAddress((void**)&p_encoded, d_encoded);
    cudaGetSymbolAddress((void**)&p_z, d_zbuf);
    cudaGetSymbolAddress((void**)&p_d1, d_d1);
    cudaGetSymbolAddress((void**)&p_recon, d_recon);
    cudaGetSymbolAddress((void**)&p_gx, d_gx);

    const size_t pipe_smem = (size_t)(Hdim + 48 * Hdim) * sizeof(float);   // 200704
    cudaFuncSetAttribute(gru_pipe_kernel, cudaFuncAttributeMaxDynamicSharedMemorySize,
                         (int)pipe_smem);

    init_kernel<<<8, 256>>>();
    gather_kernel<<<Nsamp, 256>>>(episodic, idx);

    // encoder (64x64 tiles -> 128+ CTAs, fills the chip)
    sgemm64_bias_kernel<<<dim3(H2 / BN, Nsamp / BM), 256>>>(p_samples, enc_w1, enc_b1, p_e1,
                                                            Nsamp, H2, Hdim);
    ln_gelu_kernel<<<Nsamp, 128>>>(p_e1, enc_g, enc_beta);
    sgemm64_bias_kernel<<<dim3(H2 / BN, Nsamp / BM), 256>>>(p_e1, enc_w2, enc_b2, p_encoded,
                                                            Nsamp, H2, H2);
    reparam_kernel<<<(Nsamp * Cdim) / 256, 256>>>(eps);

    // decoder (64x64 tiles)
    sgemm64_bias_kernel<<<dim3(H2 / BN, Nsamp / BM), 256>>>(p_z, dec_w1, dec_b1, p_d1,
                                                            Nsamp, H2, Cdim);
    ln_gelu_kernel<<<Nsamp, 128>>>(p_d1, dec_g, dec_beta);
    sgemm64_bias_kernel<<<dim3(Hdim / BN, Nsamp / BM), 256>>>(p_d1, dec_w2, dec_b2, p_recon,
                                                              Nsamp, Hdim, H2);

    // layer-0 input gates (big GEMM, 128x128 tiles = 192 CTAs), then pipeline
    sgemm_bias_kernel<<<dim3(G3 / TBN, Nsamp / TBM), 256>>>(p_recon, wih0, bih0, p_gx,
                                                            Nsamp, G3, Hdim);
    gru_pipe_kernel<<<2 * RCTAS, 512, pipe_smem>>>(whh0, bhh0, whh1, bhh1, wih1, bih1);

    // losses + outputs
    loss_kernel<<<Nsamp, 256>>>();
    mean_kernel<<<1, 256>>>(out);
    copy_imp_kernel<<<(Msize + 255) / 256, 256>>>(memimp, out);
    scatter_kernel<<<4, 256>>>(idx, memimp, out);
}